// round 17
// baseline (speedup 1.0000x reference)
#include <cuda_runtime.h>
#include <math.h>

#define BS_    64
#define KK_    4
#define PTS_   5
#define RES_   28
#define STEPS_ 500
#define NT_    1024
#define PIX_ (RES_*RES_)    // 784
#define HPIX_ 392
#define PSTR_ 34            // padded row stride of C partial
#define PWARP_ (32*PSTR_)   // 1088 floats per buffer
#define NBUF_  16           // 8 buffers x 2 strokes
#define SMEM_BYTES_ (NBUF_ * PWARP_ * sizeof(float))   // 69632

// staging: per-CTA pair-sum of 2 tanh-normed strokes
__device__ float g_pair[2 * BS_ * PIX_];
// per-batch pair counters (zero-init; reset by first-arriver each run)
__device__ unsigned int g_cnt[BS_];

__device__ __forceinline__ void mma_tf32(float* d,
                                         unsigned a0, unsigned a1, unsigned a2, unsigned a3,
                                         unsigned b0, unsigned b1) {
    asm volatile(
        "mma.sync.aligned.m16n8k8.row.col.f32.tf32.tf32.f32 "
        "{%0,%1,%2,%3}, {%4,%5,%6,%7}, {%8,%9}, {%0,%1,%2,%3};"
        : "+f"(d[0]), "+f"(d[1]), "+f"(d[2]), "+f"(d[3])
        : "r"(a0), "r"(a1), "r"(a2), "r"(a3), "r"(b0), "r"(b1));
}
__device__ __forceinline__ float ex2f(float x) {
    float r; asm("ex2.approx.ftz.f32 %0, %1;" : "=f"(r) : "f"(x)); return r;
}
__device__ __forceinline__ float rcpf(float x) {
    float r; asm("rcp.approx.ftz.f32 %0, %1;" : "=f"(r) : "f"(x)); return r;
}
// tanh(x) for x >= 0: 1 - 2/(exp(2x)+1)
__device__ __forceinline__ float fast_tanh(float x) {
    const float e = ex2f(x * 2.88539008177793f);
    return 1.0f - 2.0f * rcpf(e + 1.0f);
}
// exp2 of -(d*d)
__device__ __forceinline__ unsigned gauss(float d) {
    return __float_as_uint(ex2f(d * -d));
}

__global__ __launch_bounds__(NT_)
void guide_mma_kernel(const float* __restrict__ z_pres,
                      const float* __restrict__ z_what,
                      const float* __restrict__ z_where,
                      const float* __restrict__ sigma_p,
                      const float* __restrict__ slope_strk_p,
                      const float* __restrict__ slope_p,
                      float* __restrict__ out)
{
    extern __shared__ float part[];          // 16 buffers of 32x34 floats
    __shared__ float red[64];                // per-warp {max0[32], max1[32]}
    __shared__ unsigned int dummy_pad;       // (keep layout simple)

    const int bid    = blockIdx.x;           // 0..127
    const int b      = bid >> 1;
    const int pr     = bid & 1;              // k-pair: strokes {2pr, 2pr+1}
    const int bkbase = b * KK_ + pr * 2;
    const int tid  = threadIdx.x;
    const int wid  = tid >> 5;               // 0..31
    const int lane = tid & 31;
    const int gr   = lane >> 2;              // groupID 0..7
    const int tc   = lane & 3;               // thread-in-group 0..3

    // ---- hoist ALL scalar loads ----
    const float sigma = *sigma_p;
    const float sl    = *slope_strk_p;
    const float sl2   = *slope_p;
    const float zp0   = z_pres[bkbase];
    const float zp1   = z_pres[bkbase + 1];

    const float inv2  = (1.0f / (2.0f * sigma * sigma)) * 1.44269504088896f;
    const float sq    = sqrtf(inv2);         // exp = ex2(-(d*sq)^2)
    const float itsl  = rcpf(fast_tanh(sl));
    const float it2   = rcpf(fast_tanh(sl2));

    // ---- this warp's stroke: control points -> power basis (scaled by sq) ----
    const int sk  = wid & 1;
    const int grp = wid >> 1;                // 0..15, owns ksteps [grp*4, grp*4+4)
    float ax0, ax1, ax2, ax3, ax4, ay0, ay1, ay2, ay3, ay4;
    {
        const int bk = bkbase + sk;
        const float s  = z_where[bk * 3 + 0];
        const float s0 = z_where[bk * 3 + 1];
        const float s1 = z_where[bk * 3 + 2];
        const float* w = z_what + bk * PTS_ * 2;
        const float p0x = w[0]*s + s0, p0y = w[1]*s + s1;
        const float p1x = w[2]*s + s0, p1y = w[3]*s + s1;
        const float p2x = w[4]*s + s0, p2y = w[5]*s + s1;
        const float p3x = w[6]*s + s0, p3y = w[7]*s + s1;
        const float p4x = w[8]*s + s0, p4y = w[9]*s + s1;
        ax0 = p0x * sq;
        ax1 = 4.0f * (p1x - p0x) * sq;
        ax2 = 6.0f * (p2x - 2.0f*p1x + p0x) * sq;
        ax3 = 4.0f * (p3x - 3.0f*p2x + 3.0f*p1x - p0x) * sq;
        ax4 = (p4x - 4.0f*p3x + 6.0f*p2x - 4.0f*p1x + p0x) * sq;
        ay0 = p0y * sq;
        ay1 = 4.0f * (p1y - p0y) * sq;
        ay2 = 6.0f * (p2y - 2.0f*p1y + p0y) * sq;
        ay3 = 4.0f * (p3y - 3.0f*p2y + 3.0f*p1y - p0y) * sq;
        ay4 = (p4y - 4.0f*p3y + 6.0f*p2y - 4.0f*p1y + p0y) * sq;
    }

    // per-lane sqrt-scaled grid values for rows/cols {gr, gr+8, gr+16, gr+24}
    float gvs[4];
    gvs[0] = (float)gr        * (1.0f / 27.0f) * sq;
    gvs[1] = (float)(gr + 8)  * (1.0f / 27.0f) * sq;
    gvs[2] = (float)(gr + 16) * (1.0f / 27.0f) * sq;
    gvs[3] = ((gr < 4) ? (float)(gr + 24) * (1.0f / 27.0f) : 1e6f) * sq;

    float D[2][4][4];
#pragma unroll
    for (int mt = 0; mt < 2; mt++)
#pragma unroll
        for (int nt = 0; nt < 4; nt++)
#pragma unroll
            for (int r = 0; r < 4; r++) D[mt][nt][r] = 0.0f;

    // ---- mainloop: 4 ksteps, curve recomputed in-loop via Horner ----
    const int kbase = grp * 32 + tc;
#pragma unroll
    for (int j = 0; j < 4; j++) {
        float2 cA, cB;
        {
            const int k0 = kbase + j * 8;
            const float u0 = (float)k0 * (1.0f / (float)(STEPS_ - 1));
            cA.x = (((ax4*u0 + ax3)*u0 + ax2)*u0 + ax1)*u0 + ax0;
            cA.y = (((ay4*u0 + ay3)*u0 + ay2)*u0 + ay1)*u0 + ay0;
            if (k0 >= STEPS_) { cA.x = 1e9f; cA.y = 1e9f; }
            const int k1 = k0 + 4;
            const float u1 = (float)k1 * (1.0f / (float)(STEPS_ - 1));
            cB.x = (((ax4*u1 + ax3)*u1 + ax2)*u1 + ax1)*u1 + ax0;
            cB.y = (((ay4*u1 + ay3)*u1 + ay2)*u1 + ay1)*u1 + ay0;
            if (k1 >= STEPS_) { cB.x = 1e9f; cB.y = 1e9f; }
        }

        unsigned ey[4][2], ex[4][2];
#pragma unroll
        for (int r = 0; r < 4; r++) {
            ey[r][0] = gauss(gvs[r] - cA.y);
            ey[r][1] = gauss(gvs[r] - cB.y);
            ex[r][0] = gauss(gvs[r] - cA.x);
            ex[r][1] = gauss(gvs[r] - cB.x);
        }

#pragma unroll
        for (int mt = 0; mt < 2; mt++) {
            const unsigned a0 = ey[2*mt][0], a1 = ey[2*mt+1][0];
            const unsigned a2 = ey[2*mt][1], a3 = ey[2*mt+1][1];
#pragma unroll
            for (int nt = 0; nt < 4; nt++)
                mma_tf32(D[mt][nt], a0, a1, a2, a3, ex[nt][0], ex[nt][1]);
        }
    }

    // ---- staged merge: grp 8-15 store, grp 0-7 add (8 buffers per stroke) ----
    {
        float* wp = part + (sk * 8 + (grp & 7)) * PWARP_;
        if (grp >= 8) {
#pragma unroll
            for (int mt = 0; mt < 2; mt++)
#pragma unroll
                for (int nt = 0; nt < 4; nt++) {
                    const int row = mt * 16 + gr;
                    const int col = nt * 8 + 2 * tc;
                    float* b0 = wp + row * PSTR_ + col;
                    b0[0] = D[mt][nt][0];
                    b0[1] = D[mt][nt][1];
                    b0[8 * PSTR_]     = D[mt][nt][2];
                    b0[8 * PSTR_ + 1] = D[mt][nt][3];
                }
        }
        __syncthreads();
        if (grp < 8) {
#pragma unroll
            for (int mt = 0; mt < 2; mt++)
#pragma unroll
                for (int nt = 0; nt < 4; nt++) {
                    const int row = mt * 16 + gr;
                    const int col = nt * 8 + 2 * tc;
                    float* b0 = wp + row * PSTR_ + col;
                    b0[0] += D[mt][nt][0];
                    b0[1] += D[mt][nt][1];
                    b0[8 * PSTR_]     += D[mt][nt][2];
                    b0[8 * PSTR_ + 1] += D[mt][nt][3];
                }
        }
    }
    __syncthreads();

    // ---- epilogue: one pixel per thread — sum buffers, zp scale, block max ----
    float v0 = 0.0f, v1 = 0.0f;
    if (tid < PIX_) {
        const int y = tid / RES_;
        const int x = tid - y * RES_;
        const int o = y * PSTR_ + x;
        float s0 = part[o], s1 = part[8 * PWARP_ + o];
#pragma unroll
        for (int w = 1; w < 8; w++) {
            s0 += part[w * PWARP_ + o];
            s1 += part[(8 + w) * PWARP_ + o];
        }
        v0 = s0 * zp0;
        v1 = s1 * zp1;
    }
    float lmax0 = v0, lmax1 = v1;
#pragma unroll
    for (int o = 16; o > 0; o >>= 1) {
        lmax0 = fmaxf(lmax0, __shfl_xor_sync(0xffffffffu, lmax0, o));
        lmax1 = fmaxf(lmax1, __shfl_xor_sync(0xffffffffu, lmax1, o));
    }
    if (lane == 0) { red[wid] = lmax0; red[32 + wid] = lmax1; }
    __syncthreads();
    float bmax0 = red[0], bmax1 = red[32];
#pragma unroll
    for (int w = 1; w < 32; w++) {
        bmax0 = fmaxf(bmax0, red[w]);
        bmax1 = fmaxf(bmax1, red[32 + w]);
    }

    const float sc0 = rcpf(bmax0 + 1e-6f) * sl;
    const float sc1 = rcpf(bmax1 + 1e-6f) * sl;

    // pair-sum of the two tanh-normed strokes -> smem (aliases part) + global
    float* pairbuf = part;     // part fully consumed; safe after the sync above
    float* gp = g_pair + bid * PIX_;
    if (tid < PIX_) {
        const float t = (fast_tanh(v0 * sc0) + fast_tanh(v1 * sc1)) * itsl;
        pairbuf[tid] = t;
        gp[tid] = t;
    }
    __syncthreads();   // all gp/pairbuf writes done before arrival

    // ---- symmetric pair sync: arrive; first arriver spins then resets ----
    __shared__ unsigned int sgate;
    if (tid == 0) {
        unsigned int old;
        asm volatile("atom.acq_rel.gpu.global.add.u32 %0, [%1], 1;"
                     : "=r"(old) : "l"(&g_cnt[b]) : "memory");
        if (old == 0u) {
            unsigned int v;
            do {
                asm volatile("ld.acquire.gpu.global.u32 %0, [%1];"
                             : "=r"(v) : "l"(&g_cnt[b]) : "memory");
            } while (v < 2u);
            asm volatile("st.relaxed.gpu.global.u32 [%0], %1;"
                         :: "l"(&g_cnt[b]), "r"(0u) : "memory");
        }
        sgate = 1u;
        (void)dummy_pad;
    }
    __syncthreads();   // partner's data now visible to all threads

    // ---- both CTAs compose their half of the output image ----
    if (tid < HPIX_) {
        const int p = pr * HPIX_ + tid;
        const float* gq = g_pair + (bid ^ 1) * PIX_;
        const float ssum = pairbuf[p] + gq[p];
        out[b * PIX_ + p] = fast_tanh(ssum * sl2) * it2;
    }
}

extern "C" void kernel_launch(void* const* d_in, const int* in_sizes, int n_in,
                              void* d_out, int out_size)
{
    const float* z_pres     = (const float*)d_in[0];
    const float* z_what     = (const float*)d_in[1];
    const float* z_where    = (const float*)d_in[2];
    const float* sigma      = (const float*)d_in[3];
    const float* slope_strk = (const float*)d_in[4];
    const float* slope      = (const float*)d_in[5];
    float* out = (float*)d_out;

    cudaFuncSetAttribute(guide_mma_kernel,
                         cudaFuncAttributeMaxDynamicSharedMemorySize,
                         (int)SMEM_BYTES_);
    guide_mma_kernel<<<2 * BS_, NT_, SMEM_BYTES_>>>(z_pres, z_what, z_where,
                                                    sigma, slope_strk, slope, out);
}